// round 4
// baseline (speedup 1.0000x reference)
#include <cuda_runtime.h>
#include <cuda_bf16.h>

// NGP geodesic-weighted multi-level grid interpolation.
// x:[B,2] fp32 (lat,lon), embeddings:[4, 721*1441, 2] fp32, out:[B,8] fp32.
//
// Per level i (gs = 2^i, width = 1440>>i):
//   bl   = floor((clip(x) - box_min)/gs)          (exact: 1/gs is pow2)
//   idx  = bl0*width + bl1 ; corners idx, idx+1, idx+width, idx+width+1
//   wlat = geodesic ratio along lat  == (lat - gmin0)/gs   (dlon=0 => arc == |dlat|)
//   wlon = asin(|c|*sin((gmax1-lon)*r/2)) / asin(|c|*sin(gs*r/2)), c=cos(gmin0*r)
//          evaluated with 2-term Taylor for sin and asin (args <= 0.07 rad,
//          truncation error ~1e-7, tolerance 1e-3).
//   out[:, 2i:2i+2] = bilerp with (wlat, wlon) exactly as the reference combines.

#define TABLE_SIZE (721 * 1441)

__global__ __launch_bounds__(256)
void ngp_interp_kernel(const float* __restrict__ x,
                       const float* __restrict__ emb,
                       float* __restrict__ out,
                       int B)
{
    int b = blockIdx.x * blockDim.x + threadIdx.x;
    if (b >= B) return;

    const float BM0 = -90.25f;   // LAT_MIN - FINEST
    const float BM1 = -0.25f;    // LON_MIN - FINEST
    const float BX0 =  90.25f;
    const float BX1 = 360.25f;
    const float RAD = 0.017453292519943295f;   // pi/180

    float2 p  = reinterpret_cast<const float2*>(x)[b];
    float lat = p.x, lon = p.y;
    float clat = fminf(fmaxf(lat, BM0), BX0);
    float clon = fminf(fmaxf(lon, BM1), BX1);

    float res[8];

#pragma unroll
    for (int i = 0; i < 4; i++) {
        const float gs    = (float)(1 << i);
        const float inv   = 1.0f / gs;          // exact reciprocal (pow2)
        const int   width = 1440 >> i;

        int bl0 = (int)floorf((clat - BM0) * inv);
        int bl1 = (int)floorf((clon - BM1) * inv);

        float gmin0 = (float)bl0 * gs + BM0;
        float gmin1 = (float)bl1 * gs + BM1;

        int base = bl0 * width + bl1;
        const float2* tab = reinterpret_cast<const float2*>(emb) + i * TABLE_SIZE;

        // Corner gathers: two contiguous 16B pairs per cell.
        float2 e00 = __ldg(tab + base);
        float2 e01 = __ldg(tab + base + 1);
        float2 e10 = __ldg(tab + base + width);
        float2 e11 = __ldg(tab + base + width + 1);

        // wlat: geodesic along constant lon == |dlat| ratio (uses UNCLIPPED x).
        float wlat = (lat - gmin0) * inv;

        // wlon: reference numerator is the arc from lon to gmax1 (replicated).
        float dlon = (gmin1 + gs) - lon;                 // in [0, gs]
        float c    = fabsf(__cosf(gmin0 * RAD));         // |cos(lat_r)|; ratio is
                                                         // 2nd-order insensitive to c err
        float zn = dlon * (RAD * 0.5f);                  // <= 0.0699 rad
        float zd = gs   * (RAD * 0.5f);
        float sn = zn - zn * zn * zn * (1.0f / 6.0f);    // sin, rel err ~2e-7
        float sd = zd - zd * zd * zd * (1.0f / 6.0f);
        float tn = c * sn, td = c * sd;
        float tn2 = tn * tn, td2 = td * td;
        float an = tn * (1.0f + tn2 * (1.0f / 6.0f) + tn2 * tn2 * (3.0f / 40.0f)); // asin
        float ad = td * (1.0f + td2 * (1.0f / 6.0f) + td2 * td2 * (3.0f / 40.0f));
        float wlon = an / ad;

        // Bilinear combine, matching reference:
        //   c0 = e00*(1-wlat)+e10*wlat ; c1 = e01*(1-wlat)+e11*wlat
        //   out = c0*(1-wlon)+c1*wlon
        float c0x = fmaf(e10.x - e00.x, wlat, e00.x);
        float c0y = fmaf(e10.y - e00.y, wlat, e00.y);
        float c1x = fmaf(e11.x - e01.x, wlat, e01.x);
        float c1y = fmaf(e11.y - e01.y, wlat, e01.y);

        res[2 * i + 0] = fmaf(c1x - c0x, wlon, c0x);
        res[2 * i + 1] = fmaf(c1y - c0y, wlon, c0y);
    }

    float4* o = reinterpret_cast<float4*>(out) + (size_t)b * 2;
    o[0] = make_float4(res[0], res[1], res[2], res[3]);
    o[1] = make_float4(res[4], res[5], res[6], res[7]);
}

extern "C" void kernel_launch(void* const* d_in, const int* in_sizes, int n_in,
                              void* d_out, int out_size)
{
    const float* x   = (const float*)d_in[0];
    const float* emb = (const float*)d_in[1];
    float*       out = (float*)d_out;

    int B = in_sizes[0] / 2;
    int threads = 256;
    int blocks  = (B + threads - 1) / threads;
    ngp_interp_kernel<<<blocks, threads>>>(x, emb, out, B);
}

// round 5
// speedup vs baseline: 1.1027x; 1.1027x over previous
#include <cuda_runtime.h>
#include <cuda_bf16.h>

// NGP geodesic-weighted multi-level grid interpolation — pair-layout version.
//
// Pass 1 (build_pairs): for each level, build a 16B-aligned row-pair table
//   pairs[j] = { emb[j].xy, emb[j+1].xy }
// over only the index range reachable from the clipped input domain
// (bl0 <= floor(180.5/gs)). Total scratch: 347,568 float4 = 5.56 MB.
//
// Pass 2 (interp): per point per level, TWO aligned LDG.128 gathers
// (top row pair, bottom row pair) replace four LDG.64 gathers, halving
// L1tex wavefronts, which profiling showed to be the bottleneck.

#define TABLE_SIZE (721 * 1441)

// Reachable pair-range per level (bl0_max*width + bl1_max + width + slack):
//   L0: 180*1440+360 +1440 -> 261008
//   L1:  90* 720+180 + 720 ->  65712
//   L2:  45* 360+ 90 + 360 ->  16656
//   L3:  22* 180+ 45 + 180 ->   4192
#define NP0 261008
#define NP1 65712
#define NP2 16656
#define NP3 4192
#define OFF0 0
#define OFF1 (NP0)
#define OFF2 (NP0 + NP1)
#define OFF3 (NP0 + NP1 + NP2)
#define NPAIRS (NP0 + NP1 + NP2 + NP3)

__device__ float4 g_pairs[NPAIRS];

__global__ __launch_bounds__(256)
void build_pairs(const float* __restrict__ emb)
{
    int t = blockIdx.x * blockDim.x + threadIdx.x;
    if (t >= NPAIRS) return;

    int level, j;
    if (t < OFF1)      { level = 0; j = t; }
    else if (t < OFF2) { level = 1; j = t - OFF1; }
    else if (t < OFF3) { level = 2; j = t - OFF2; }
    else               { level = 3; j = t - OFF3; }

    const float2* tab = reinterpret_cast<const float2*>(emb) + level * TABLE_SIZE;
    float2 a = __ldg(tab + j);
    float2 b = __ldg(tab + j + 1);
    g_pairs[t] = make_float4(a.x, a.y, b.x, b.y);
}

__global__ __launch_bounds__(256)
void ngp_interp_kernel(const float* __restrict__ x,
                       float* __restrict__ out,
                       int B)
{
    int b = blockIdx.x * blockDim.x + threadIdx.x;
    if (b >= B) return;

    const float BM0 = -90.25f;   // LAT_MIN - FINEST
    const float BM1 = -0.25f;    // LON_MIN - FINEST
    const float BX0 =  90.25f;
    const float BX1 = 360.25f;
    const float RAD = 0.017453292519943295f;   // pi/180

    float2 p  = reinterpret_cast<const float2*>(x)[b];
    float lat = p.x, lon = p.y;
    float clat = fminf(fmaxf(lat, BM0), BX0);
    float clon = fminf(fmaxf(lon, BM1), BX1);

    const int   widths[4]  = {1440, 720, 360, 180};
    const int   poff[4]    = {OFF0, OFF1, OFF2, OFF3};

    // Phase 1: compute all indices and issue all 8 gathers (max MLP).
    int   bl0a[4], bl1a[4];
    float4 lo[4], hi[4];
#pragma unroll
    for (int i = 0; i < 4; i++) {
        const float gs  = (float)(1 << i);
        const float inv = 1.0f / gs;            // exact (pow2)
        const int   width = widths[i];

        int bl0 = (int)floorf((clat - BM0) * inv);
        int bl1 = (int)floorf((clon - BM1) * inv);
        bl0a[i] = bl0; bl1a[i] = bl1;

        int base = poff[i] + bl0 * width + bl1;
        lo[i] = __ldg(&g_pairs[base]);          // {e00, e01}
        hi[i] = __ldg(&g_pairs[base + width]);  // {e10, e11}
    }

    // Phase 2: weights + bilinear combine.
    float res[8];
#pragma unroll
    for (int i = 0; i < 4; i++) {
        const float gs  = (float)(1 << i);
        const float inv = 1.0f / gs;

        float gmin0 = (float)bl0a[i] * gs + BM0;
        float gmin1 = (float)bl1a[i] * gs + BM1;

        // wlat: geodesic along constant lon == |dlat|/gs (uses UNCLIPPED lat).
        float wlat = (lat - gmin0) * inv;

        // wlon: asin(|c| sin((gmax1-lon)r/2)) / asin(|c| sin(gs r/2)),
        // args <= 0.07 rad -> 2-term Taylor, rel err ~2e-7.
        float dlon = (gmin1 + gs) - lon;
        float c    = fabsf(__cosf(gmin0 * RAD));
        float zn = dlon * (RAD * 0.5f);
        float zd = gs   * (RAD * 0.5f);
        float sn = zn - zn * zn * zn * (1.0f / 6.0f);
        float sd = zd - zd * zd * zd * (1.0f / 6.0f);
        float tn = c * sn, td = c * sd;
        float tn2 = tn * tn, td2 = td * td;
        float an = tn * (1.0f + tn2 * (1.0f / 6.0f) + tn2 * tn2 * (3.0f / 40.0f));
        float ad = td * (1.0f + td2 * (1.0f / 6.0f) + td2 * td2 * (3.0f / 40.0f));
        float wlon = an / ad;

        float e00x = lo[i].x, e00y = lo[i].y, e01x = lo[i].z, e01y = lo[i].w;
        float e10x = hi[i].x, e10y = hi[i].y, e11x = hi[i].z, e11y = hi[i].w;

        float c0x = fmaf(e10x - e00x, wlat, e00x);
        float c0y = fmaf(e10y - e00y, wlat, e00y);
        float c1x = fmaf(e11x - e01x, wlat, e01x);
        float c1y = fmaf(e11y - e01y, wlat, e01y);

        res[2 * i + 0] = fmaf(c1x - c0x, wlon, c0x);
        res[2 * i + 1] = fmaf(c1y - c0y, wlon, c0y);
    }

    float4* o = reinterpret_cast<float4*>(out) + (size_t)b * 2;
    o[0] = make_float4(res[0], res[1], res[2], res[3]);
    o[1] = make_float4(res[4], res[5], res[6], res[7]);
}

extern "C" void kernel_launch(void* const* d_in, const int* in_sizes, int n_in,
                              void* d_out, int out_size)
{
    const float* x   = (const float*)d_in[0];
    const float* emb = (const float*)d_in[1];
    float*       out = (float*)d_out;

    int B = in_sizes[0] / 2;

    build_pairs<<<(NPAIRS + 255) / 256, 256>>>(emb);

    int threads = 256;
    int blocks  = (B + threads - 1) / threads;
    ngp_interp_kernel<<<blocks, threads>>>(x, out, B);
}